// round 1
// baseline (speedup 1.0000x reference)
#include <cuda_runtime.h>

// neigh_Conv: out[n,c,h,w] = b[c] + sum_{k<8} W[c,k] * x[n,c+k,h,w]
// x: (16, 200, 128, 128) f32, W: (193, 8) f32, b: (193,) f32
// out: (16, 193, 128, 128) f32
//
// Strategy: HBM-bound streaming. Each thread owns 4 consecutive w-positions
// (float4) of one (n, h) column and slides a 16-deep register ring over the
// 200 input channels (prefetch distance 8). x is read exactly once, out
// written exactly once -> 412 MB minimum traffic. W/b live in shared memory,
// fetched as broadcast LDS.128 pairs per output channel.

#define HW4   4096   // 128*128 / 4 float4 per plane
#define CIN   200
#define OUTC  193
#define RING  16

__global__ __launch_bounds__(256, 2)
void neigh_conv_kernel(const float4* __restrict__ x,
                       const float4* __restrict__ W4,   // 193*8 floats = 386 float4
                       const float*  __restrict__ b,
                       float4* __restrict__ out) {
    __shared__ float4 sW[OUTC * 2];   // W row oc -> sW[2*oc], sW[2*oc+1]
    __shared__ float  sB[OUTC];

    const int t = threadIdx.x;
    for (int i = t; i < OUTC * 2; i += blockDim.x) sW[i] = W4[i];
    for (int i = t; i < OUTC;     i += blockDim.x) sB[i] = b[i];
    __syncthreads();

    const int gid = blockIdx.x * blockDim.x + t;     // 0 .. 65535
    const int n   = gid >> 12;                       // / 4096
    const int pos = gid & 4095;

    const float4* xin = x   + (size_t)n * CIN  * HW4 + pos;
    float4*       op  = out + (size_t)n * OUTC * HW4 + pos;

    // Register ring: before iteration oc it holds x[oc .. oc+14].
    float4 win[RING];
#pragma unroll
    for (int i = 0; i < RING - 1; ++i)
        win[i] = __ldcs(xin + (size_t)i * HW4);

    // Trip count 200 (multiple of 8) so unroll-by-8 keeps all ring indices
    // static (no local-memory spill). Guards: prefetch only while c < 200,
    // store only while oc < 193.
#pragma unroll 8
    for (int oc = 0; oc < CIN; ++oc) {
        // Prefetch x[oc+15], consumed 8 iterations later.
        if (oc < CIN - (RING - 1))
            win[(oc + RING - 1) & (RING - 1)] =
                __ldcs(xin + (size_t)(oc + RING - 1) * HW4);

        if (oc < OUTC) {
            const float4 w0 = sW[oc * 2];
            const float4 w1 = sW[oc * 2 + 1];
            const float  wk[8] = {w0.x, w0.y, w0.z, w0.w,
                                  w1.x, w1.y, w1.z, w1.w};
            const float bb = sB[oc];
            float4 acc = make_float4(bb, bb, bb, bb);
#pragma unroll
            for (int k = 0; k < 8; ++k) {
                const float4 xv = win[(oc + k) & (RING - 1)];
                acc.x = fmaf(wk[k], xv.x, acc.x);
                acc.y = fmaf(wk[k], xv.y, acc.y);
                acc.z = fmaf(wk[k], xv.z, acc.z);
                acc.w = fmaf(wk[k], xv.w, acc.w);
            }
            __stcs(op + (size_t)oc * HW4, acc);
        }
    }
}

extern "C" void kernel_launch(void* const* d_in, const int* in_sizes, int n_in,
                              void* d_out, int out_size) {
    const float4* x  = (const float4*)d_in[0];
    const float4* W4 = (const float4*)d_in[1];
    const float*  b  = (const float*)d_in[2];
    float4* out = (float4*)d_out;

    // 16 images * 4096 float4 per plane = 65536 threads
    neigh_conv_kernel<<<65536 / 256, 256>>>(x, W4, b, out);
}